// round 3
// baseline (speedup 1.0000x reference)
#include <cuda_runtime.h>
#include <math.h>

#define BB    8
#define CCH   64
#define C2    128
#define HH    224
#define WWID  224
#define HWSZ  (HH*WWID)          // 50176
#define NPIX  (BB*HWSZ)          // 401408

// ---------------- scratch (device globals; no allocation allowed) ----------------
static __device__ float g_buf2a[BB*C2*HWSZ];   // 205.5 MB
static __device__ float g_buf2b[BB*C2*HWSZ];   // 205.5 MB
static __device__ float g_bufc [BB*CCH*HWSZ];  // 102.8 MB
static __device__ float g_y    [BB*CCH*HWSZ];  // 102.8 MB
static __device__ float g_M    [C2*64*64];     // per-channel 64x64 patch-spectral matrix
static __device__ float g_dctR [CCH*56];
static __device__ float g_dctC [CCH*56];
static __device__ float g_instS[BB*CCH], g_instQ[BB*CCH];
static __device__ float g_instMean[BB*CCH], g_instInv[BB*CCH];
static __device__ float g_scay[BB*CCH], g_z[BB*CCH];

// ---------------- tiny init kernels ----------------
__global__ void k_zero() {
    int t = threadIdx.x;
    if (t < BB*CCH) { g_instS[t] = 0.f; g_instQ[t] = 0.f; g_scay[t] = 0.f; }
}

__global__ void k_tables() {
    int t = blockIdx.x * blockDim.x + threadIdx.x;
    if (t >= CCH*56) return;
    int c = t / 56, i = t - c*56;
    const int mx[16] = {0,0,6,0,0,1,1,4,5,1,3,0,0,0,3,2};
    const int my[16] = {0,1,0,5,2,0,2,0,0,6,0,4,6,3,2,5};
    int g = c >> 2;                      // part = 64/16 = 4
    int ux = mx[g]*8, uy = my[g]*8;      // sx = sy = 56/7 = 8
    float inv = rsqrtf(56.f);
    float rv = cosf((float)M_PI * ux * (i + 0.5f) / 56.f) * inv;
    if (ux) rv *= 1.41421356237f;
    float cv = cosf((float)M_PI * uy * (i + 0.5f) / 56.f) * inv;
    if (uy) cv *= 1.41421356237f;
    g_dctR[t] = rv; g_dctC[t] = cv;
}

// Build M_c: push each delta basis (i0,j0) through fft(ax-2) -> rfft(ax-1) -> *W ->
// ifft(ax-2) -> irfft(ax-1).  (Exact twiddles via 8-entry tables; W=ones => identity.)
__global__ void k_fftmat(const float* __restrict__ fw) {
    int t = blockIdx.x * blockDim.x + threadIdx.x;   // 8192 threads
    if (t >= C2*64) return;
    int c = t >> 6, in = t & 63, i0 = in >> 3, j0 = in & 7;
    const float c8[8] = {1.f, 0.70710678118f, 0.f, -0.70710678118f,
                         -1.f, -0.70710678118f, 0.f, 0.70710678118f};
    const float s8[8] = {0.f, 0.70710678118f, 1.f, 0.70710678118f,
                         0.f, -0.70710678118f, -1.f, -0.70710678118f};
    for (int p = 0; p < 8; p++) {
        float Gr[5], Gi[5];
        for (int v = 0; v < 5; v++) {
            float gr = 0.f, gi = 0.f;
            for (int u = 0; u < 8; u++) {
                int idx = ((u*(p - i0) - v*j0) % 8 + 8) % 8;  // phase 2*pi*idx/8
                float w = fw[c*40 + u*5 + v];
                gr += w * c8[idx]; gi += w * s8[idx];
            }
            Gr[v] = gr; Gi[v] = gi;
        }
        for (int q = 0; q < 8; q++) {
            float val = Gr[0] + ((q & 1) ? -Gr[4] : Gr[4]);   // DC + Nyquist (real parts)
            for (int v = 1; v < 4; v++) {
                int k = (v*q) & 7;
                val += 2.f * (Gr[v]*c8[k] - Gi[v]*s8[k]);
            }
            g_M[c*4096 + (p*8 + q)*64 + in] = val * (1.f/64.f);
        }
    }
}

// ---------------- per-pixel LN(channel) + conv1x1 (64 -> OC) ----------------
__global__ __launch_bounds__(128) void k_lnmm(
    const float* __restrict__ in, const float* __restrict__ w,
    const float* __restrict__ bias, const float* __restrict__ lnw,
    const float* __restrict__ lnb, float eps, float* __restrict__ out, int OC)
{
    __shared__ float4 sw[C2*16];
    __shared__ float slw[64], slb[64], sb[C2];
    int tid = threadIdx.x;
    const float4* w4 = (const float4*)w;
    for (int i = tid; i < OC*16; i += 128) sw[i] = w4[i];
    if (tid < 64) { slw[tid] = lnw[tid]; slb[tid] = lnb[tid]; }
    if (bias) for (int i = tid; i < OC; i += 128) sb[i] = bias[i];
    __syncthreads();

    int pix = blockIdx.x*128 + tid;
    int b = pix / HWSZ, hw = pix - b*HWSZ;
    const float* src = in + b*CCH*HWSZ + hw;
    float v[64];
#pragma unroll
    for (int c = 0; c < 64; c++) v[c] = src[c*HWSZ];
    float mu = 0.f;
#pragma unroll
    for (int c = 0; c < 64; c++) mu += v[c];
    mu *= (1.f/64.f);
    float var = 0.f;
#pragma unroll
    for (int c = 0; c < 64; c++) { float d = v[c]-mu; var += d*d; }
    var *= (1.f/64.f);
    float is = rsqrtf(var + eps);
#pragma unroll
    for (int c = 0; c < 64; c++) v[c] = (v[c]-mu)*is*slw[c] + slb[c];

    float* dst = out + b*OC*HWSZ + hw;
    for (int o = 0; o < OC; o++) {
        const float4* wr = &sw[o*16];
        float a0=0.f, a1=0.f, a2=0.f, a3=0.f;
#pragma unroll
        for (int k = 0; k < 16; k++) {
            float4 ww = wr[k];
            a0 += ww.x*v[4*k];   a1 += ww.y*v[4*k+1];
            a2 += ww.z*v[4*k+2]; a3 += ww.w*v[4*k+3];
        }
        float acc = (a0+a1)+(a2+a3);
        if (bias) acc += sb[o];
        dst[o*HWSZ] = acc;
    }
}

// ---------------- depthwise 3x3 (+bias) with optional InstanceNorm stats ----------------
__global__ __launch_bounds__(256) void k_dw_stats(
    const float* __restrict__ in, const float* __restrict__ w,
    const float* __restrict__ bias, float* __restrict__ out)
{
    int bc = blockIdx.z;                 // b*128 + c
    int c = bc & 127, b = bc >> 7;
    __shared__ float tile[10][34];
    __shared__ float redS[256], redQ[256];
    int tx0 = blockIdx.x*32, ty0 = blockIdx.y*8;
    int tid = threadIdx.y*32 + threadIdx.x;
    const float* src = in + bc*HWSZ;
    for (int i = tid; i < 340; i += 256) {
        int r = i/34, cc = i - r*34;
        int gy = ty0 + r - 1, gx = tx0 + cc - 1;
        tile[r][cc] = (gy >= 0 && gy < HH && gx >= 0 && gx < WWID) ? src[gy*WWID+gx] : 0.f;
    }
    __syncthreads();
    float acc = bias[c];
#pragma unroll
    for (int di = 0; di < 3; di++)
#pragma unroll
        for (int dj = 0; dj < 3; dj++)
            acc += w[c*9 + di*3 + dj] * tile[threadIdx.y+di][threadIdx.x+dj];
    out[bc*HWSZ + (ty0+threadIdx.y)*WWID + tx0 + threadIdx.x] = acc;

    if (c < 64) {                         // stats for the 'a' half (InstanceNorm)
        redS[tid] = acc; redQ[tid] = acc*acc;
        __syncthreads();
        for (int s = 128; s > 0; s >>= 1) {
            if (tid < s) { redS[tid] += redS[tid+s]; redQ[tid] += redQ[tid+s]; }
            __syncthreads();
        }
        if (tid == 0) {
            atomicAdd(&g_instS[b*64 + c], redS[0]);
            atomicAdd(&g_instQ[b*64 + c], redQ[0]);
        }
    }
}

__global__ void k_instfin() {
    int t = blockIdx.x*blockDim.x + threadIdx.x;
    if (t < BB*CCH) {
        float m = g_instS[t] * (1.f/HWSZ);
        float v = g_instQ[t] * (1.f/HWSZ) - m*m;
        g_instMean[t] = m;
        g_instInv[t]  = rsqrtf(v + 1e-5f);
    }
}

// ---------------- instnorm(a)*g, write t3, accumulate DCT-weighted SCA pool ----------------
__global__ __launch_bounds__(256) void k_gate_sca(
    const float* __restrict__ inw, const float* __restrict__ inb)
{
    int bc = blockIdx.y;                 // b*64 + c
    int c = bc & 63, b = bc >> 6;
    int idx = blockIdx.x*256 + threadIdx.x;
    const float* A = g_buf2b + (b*128 + c)*HWSZ;
    const float* G = g_buf2b + (b*128 + 64 + c)*HWSZ;
    float m = g_instMean[bc], iv = g_instInv[bc];
    float a = A[idx], g = G[idx];
    float t3 = ((a - m)*iv*inw[c] + inb[c]) * g;
    g_bufc[bc*HWSZ + idx] = t3;
    int gy = idx / WWID, gx = idx - gy*WWID;
    float ws = t3 * g_dctR[c*56 + (gy >> 2)] * g_dctC[c*56 + (gx >> 2)];
    __shared__ float red[256];
    red[threadIdx.x] = ws; __syncthreads();
    for (int s = 128; s > 0; s >>= 1) {
        if (threadIdx.x < s) red[threadIdx.x] += red[threadIdx.x+s];
        __syncthreads();
    }
    if (threadIdx.x == 0) atomicAdd(&g_scay[bc], red[0]);
}

__global__ void k_se(const float* __restrict__ fc1, const float* __restrict__ fc2) {
    int b = blockIdx.x, c = threadIdx.x;
    __shared__ float ys[64];
    ys[c] = g_scay[b*64 + c] * (1.f/16.f);     // 4x4 avg-pool factor
    __syncthreads();
    float h[4];
#pragma unroll
    for (int j = 0; j < 4; j++) {
        float s = 0.f;
#pragma unroll
        for (int k = 0; k < 64; k++) s += fc1[j*64 + k] * ys[k];
        h[j] = fmaxf(s, 0.f);
    }
    float z = 0.f;
#pragma unroll
    for (int j = 0; j < 4; j++) z += fc2[c*4 + j] * h[j];
    g_z[b*64 + c] = 1.f / (1.f + expf(-z));
}

// ---------------- (t3 * z) -> conv3 + bias -> residual = x + beta*(.) ----------------
__global__ __launch_bounds__(128) void k_conv3_res(
    const float* __restrict__ x, const float* __restrict__ w,
    const float* __restrict__ bias, const float* __restrict__ beta)
{
    __shared__ float4 sw[64*16];
    __shared__ float sb[64], sbt[64], sz[64];
    int tid = threadIdx.x;
    const float4* w4 = (const float4*)w;
    for (int i = tid; i < 1024; i += 128) sw[i] = w4[i];
    int pix = blockIdx.x*128 + tid;
    int b = pix / HWSZ, hw = pix - b*HWSZ;
    if (tid < 64) { sb[tid] = bias[tid]; sbt[tid] = beta[tid]; sz[tid] = g_z[b*64 + tid]; }
    __syncthreads();
    const float* t3 = g_bufc + b*CCH*HWSZ + hw;
    const float* xs = x      + b*CCH*HWSZ + hw;
    float v[64];
#pragma unroll
    for (int c = 0; c < 64; c++) v[c] = t3[c*HWSZ] * sz[c];
    float* dst = g_buf2a + b*CCH*HWSZ + hw;     // residual buffer (C layout)
    for (int o = 0; o < 64; o++) {
        const float4* wr = &sw[o*16];
        float a0=0.f,a1=0.f,a2=0.f,a3=0.f;
#pragma unroll
        for (int k = 0; k < 16; k++) {
            float4 ww = wr[k];
            a0 += ww.x*v[4*k];   a1 += ww.y*v[4*k+1];
            a2 += ww.z*v[4*k+2]; a3 += ww.w*v[4*k+3];
        }
        float t4 = (a0+a1)+(a2+a3) + sb[o];
        dst[o*HWSZ] = xs[o*HWSZ] + sbt[o]*t4;
    }
}

// ---------------- LN(residual) -> conv4 (64->128) -> SimpleGate ----------------
__global__ __launch_bounds__(128) void k_ln_gate(
    const float* __restrict__ w4c, const float* __restrict__ b4,
    const float* __restrict__ lnw, const float* __restrict__ lnb)
{
    __shared__ float4 sw[128*16];
    __shared__ float sb[128], slw[64], slb[64];
    int tid = threadIdx.x;
    const float4* wv = (const float4*)w4c;
    for (int i = tid; i < 2048; i += 128) sw[i] = wv[i];
    if (tid < 64) { slw[tid] = lnw[tid]; slb[tid] = lnb[tid]; }
    sb[tid] = b4[tid];
    __syncthreads();

    int pix = blockIdx.x*128 + tid;
    int b = pix / HWSZ, hw = pix - b*HWSZ;
    const float* src = g_buf2a + b*CCH*HWSZ + hw;
    float v[64];
#pragma unroll
    for (int c = 0; c < 64; c++) v[c] = src[c*HWSZ];
    float mu = 0.f;
#pragma unroll
    for (int c = 0; c < 64; c++) mu += v[c];
    mu *= (1.f/64.f);
    float var = 0.f;
#pragma unroll
    for (int c = 0; c < 64; c++) { float d = v[c]-mu; var += d*d; }
    var *= (1.f/64.f);
    float is = rsqrtf(var + 1e-6f);
#pragma unroll
    for (int c = 0; c < 64; c++) v[c] = (v[c]-mu)*is*slw[c] + slb[c];

    float* dst = g_bufc + b*CCH*HWSZ + hw;
    for (int o = 0; o < 64; o++) {
        const float4* r1 = &sw[o*16];
        const float4* r2 = &sw[(o+64)*16];
        float p0=0.f,p1=0.f,p2=0.f,p3=0.f,q0=0.f,q1=0.f,q2=0.f,q3=0.f;
#pragma unroll
        for (int k = 0; k < 16; k++) {
            float4 wa = r1[k], wb = r2[k];
            p0 += wa.x*v[4*k];   p1 += wa.y*v[4*k+1];
            p2 += wa.z*v[4*k+2]; p3 += wa.w*v[4*k+3];
            q0 += wb.x*v[4*k];   q1 += wb.y*v[4*k+1];
            q2 += wb.z*v[4*k+2]; q3 += wb.w*v[4*k+3];
        }
        float A  = (p0+p1)+(p2+p3) + sb[o];
        float Bv = (q0+q1)+(q2+q3) + sb[o+64];
        dst[o*HWSZ] = A*Bv;
    }
}

// ---------------- generic per-pixel 64x64 matmul (+bias, +add) ----------------
__global__ __launch_bounds__(128) void k_mm64(
    const float* __restrict__ in, const float* __restrict__ w,
    const float* __restrict__ bias, const float* __restrict__ add,
    float* __restrict__ out)
{
    __shared__ float4 sw[64*16];
    __shared__ float sb[64];
    int tid = threadIdx.x;
    const float4* w4 = (const float4*)w;
    for (int i = tid; i < 1024; i += 128) sw[i] = w4[i];
    if (bias && tid < 64) sb[tid] = bias[tid];
    __syncthreads();
    int pix = blockIdx.x*128 + tid;
    int b = pix / HWSZ, hw = pix - b*HWSZ;
    const float* src = in + b*CCH*HWSZ + hw;
    float v[64];
#pragma unroll
    for (int c = 0; c < 64; c++) v[c] = src[c*HWSZ];
    const float* ads = add ? (add + b*CCH*HWSZ + hw) : nullptr;
    float* dst = out + b*CCH*HWSZ + hw;
    for (int o = 0; o < 64; o++) {
        const float4* wr = &sw[o*16];
        float a0=0.f,a1=0.f,a2=0.f,a3=0.f;
#pragma unroll
        for (int k = 0; k < 16; k++) {
            float4 ww = wr[k];
            a0 += ww.x*v[4*k];   a1 += ww.y*v[4*k+1];
            a2 += ww.z*v[4*k+2]; a3 += ww.w*v[4*k+3];
        }
        float acc = (a0+a1)+(a2+a3);
        if (bias) acc += sb[o];
        if (add)  acc += ads[o*HWSZ];
        dst[o*HWSZ] = acc;
    }
}

// ---------------- per-patch spectral transform: out = M_c @ patch ----------------
__global__ __launch_bounds__(256) void k_fftapply() {
    int pr = blockIdx.x;                 // patch row band 0..27
    int bc = blockIdx.y;                 // b*128 + c
    int c  = bc & 127;
    __shared__ float Ms[4096];
    __shared__ float pat[28][64];
    int tid = threadIdx.x;
    const float* msrc = g_M + c*4096;
    for (int i = tid; i < 4096; i += 256) Ms[i] = msrc[i];
    const float* src = g_buf2b + bc*HWSZ + pr*8*WWID;
    for (int i = tid; i < 1792; i += 256) {
        int p = i / WWID, w = i - p*WWID;
        pat[w >> 3][p*8 + (w & 7)] = src[p*WWID + w];
    }
    __syncthreads();
    float* dst = g_buf2a + bc*HWSZ + pr*8*WWID;
    for (int i = tid; i < 1792; i += 256) {
        int p = i / WWID, w = i - p*WWID;
        int pc = w >> 3, oi = p*8 + (w & 7);
        const float4* mr = (const float4*)&Ms[oi*64];
        const float4* pv = (const float4*)&pat[pc][0];
        float a0=0.f,a1=0.f,a2=0.f,a3=0.f;
#pragma unroll
        for (int k = 0; k < 16; k++) {
            float4 m = mr[k], x = pv[k];
            a0 += m.x*x.x; a1 += m.y*x.y; a2 += m.z*x.z; a3 += m.w*x.w;
        }
        dst[p*WWID + w] = (a0+a1)+(a2+a3);
    }
}

// ---------------- DFFN depthwise 3x3 pair + gelu gate ----------------
__global__ __launch_bounds__(256) void k_dw_gelu(const float* __restrict__ w) {
    int bc = blockIdx.z;                 // b*64 + c
    int c = bc & 63, b = bc >> 6;
    __shared__ float t1[10][34], t2[10][34];
    int tx0 = blockIdx.x*32, ty0 = blockIdx.y*8;
    int tid = threadIdx.y*32 + threadIdx.x;
    const float* s1 = g_buf2a + (b*128 + c)*HWSZ;
    const float* s2 = g_buf2a + (b*128 + 64 + c)*HWSZ;
    for (int i = tid; i < 340; i += 256) {
        int r = i/34, cc = i - r*34;
        int gy = ty0 + r - 1, gx = tx0 + cc - 1;
        bool ok = (gy >= 0 && gy < HH && gx >= 0 && gx < WWID);
        t1[r][cc] = ok ? s1[gy*WWID+gx] : 0.f;
        t2[r][cc] = ok ? s2[gy*WWID+gx] : 0.f;
    }
    __syncthreads();
    float d1 = 0.f, d2 = 0.f;
#pragma unroll
    for (int di = 0; di < 3; di++)
#pragma unroll
        for (int dj = 0; dj < 3; dj++) {
            d1 += w[c*9 + di*3 + dj]      * t1[threadIdx.y+di][threadIdx.x+dj];
            d2 += w[(64+c)*9 + di*3 + dj] * t2[threadIdx.y+di][threadIdx.x+dj];
        }
    float gel = 0.5f * d1 * (1.f + erff(d1 * 0.70710678118f));   // exact gelu
    g_bufc[bc*HWSZ + (ty0+threadIdx.y)*WWID + tx0 + threadIdx.x] = gel * d2;
}

// ---------------- launch ----------------
extern "C" void kernel_launch(void* const* d_in, const int* in_sizes, int n_in,
                              void* d_out, int out_size)
{
    (void)in_sizes; (void)n_in; (void)out_size;
    const float* x       = (const float*)d_in[0];
    const float* n1_w    = (const float*)d_in[1];
    const float* n1_b    = (const float*)d_in[2];
    const float* conv1_w = (const float*)d_in[3];
    const float* conv1_b = (const float*)d_in[4];
    const float* conv2_w = (const float*)d_in[5];
    const float* conv2_b = (const float*)d_in[6];
    const float* in_w    = (const float*)d_in[7];
    const float* in_b    = (const float*)d_in[8];
    const float* fc1_w   = (const float*)d_in[9];
    const float* fc2_w   = (const float*)d_in[10];
    const float* conv3_w = (const float*)d_in[11];
    const float* conv3_b = (const float*)d_in[12];
    const float* beta    = (const float*)d_in[13];
    const float* n2n_w   = (const float*)d_in[14];
    const float* n2n_b   = (const float*)d_in[15];
    const float* conv4_w = (const float*)d_in[16];
    const float* conv4_b = (const float*)d_in[17];
    const float* conv5_w = (const float*)d_in[18];
    const float* conv5_b = (const float*)d_in[19];
    const float* ln_w    = (const float*)d_in[20];
    const float* ln_b    = (const float*)d_in[21];
    const float* pin_w   = (const float*)d_in[22];
    const float* dw_w    = (const float*)d_in[23];
    const float* fft_w   = (const float*)d_in[24];
    const float* pout_w  = (const float*)d_in[25];

    float *t2a, *t2b, *tc, *ty;
    cudaGetSymbolAddress((void**)&t2a, g_buf2a);
    cudaGetSymbolAddress((void**)&t2b, g_buf2b);
    cudaGetSymbolAddress((void**)&tc,  g_bufc);
    cudaGetSymbolAddress((void**)&ty,  g_y);

    const int PBLK = NPIX / 128;   // 3136

    k_zero<<<1, 512>>>();
    k_tables<<<28, 128>>>();
    k_fftmat<<<64, 128>>>(fft_w);

    // NAFBlock part 1: LN(n1) + conv1 (64->128)
    k_lnmm<<<PBLK, 128>>>(x, conv1_w, conv1_b, n1_w, n1_b, 1e-6f, t2a, 128);

    // depthwise 3x3 + conv2 bias, InstanceNorm stats on 'a' half
    {
        dim3 g(7, 28, BB*C2), blk(32, 8);
        k_dw_stats<<<g, blk>>>(t2a, conv2_w, conv2_b, t2b);
    }
    k_instfin<<<4, 128>>>();

    // instnorm(a)*g -> t3, DCT-weighted SCA pooling
    {
        dim3 g(HWSZ/256, BB*CCH);
        k_gate_sca<<<g, 256>>>(in_w, in_b);
    }
    k_se<<<BB, 64>>>(fc1_w, fc2_w);

    // (t3*z) conv3 + residual
    k_conv3_res<<<PBLK, 128>>>(x, conv3_w, conv3_b, beta);
    // LN(n2n) + conv4 + SimpleGate
    k_ln_gate<<<PBLK, 128>>>(conv4_w, conv4_b, n2n_w, n2n_b);
    // conv5 -> y (NAF output)
    k_mm64<<<PBLK, 128>>>(tc, conv5_w, conv5_b, nullptr, ty);

    // DFFN: LN + pin (64->128)
    k_lnmm<<<PBLK, 128>>>(ty, pin_w, nullptr, ln_w, ln_b, 1e-5f, t2b, 128);
    // patch spectral transform
    {
        dim3 g(28, BB*C2);
        k_fftapply<<<g, 256>>>();
    }
    // depthwise pair + gelu gate
    {
        dim3 g(7, 28, BB*CCH), blk(32, 8);
        k_dw_gelu<<<g, blk>>>(dw_w);
    }
    // pout + y -> d_out
    k_mm64<<<PBLK, 128>>>(tc, pout_w, nullptr, ty, (float*)d_out);
}

// round 4
// speedup vs baseline: 2.1429x; 2.1429x over previous
#include <cuda_runtime.h>
#include <math.h>

#define BB    8
#define CCH   64
#define C2    128
#define HH    224
#define WWID  224
#define HWSZ  (HH*WWID)          // 50176
#define NPIX  (BB*HWSZ)          // 401408

typedef unsigned long long ull;

// ---------------- packed f32x2 helpers ----------------
__device__ __forceinline__ ull pack2(float x) {
    ull r; asm("mov.b64 %0, {%1, %1};" : "=l"(r) : "f"(x)); return r;
}
__device__ __forceinline__ ull fma2(ull a, ull b, ull c) {
    ull d; asm("fma.rn.f32x2 %0, %1, %2, %3;" : "=l"(d) : "l"(a), "l"(b), "l"(c)); return d;
}
__device__ __forceinline__ ull add2(ull a, ull b) {
    ull d; asm("add.rn.f32x2 %0, %1, %2;" : "=l"(d) : "l"(a), "l"(b)); return d;
}
__device__ __forceinline__ ull mul2(ull a, ull b) {
    ull d; asm("mul.rn.f32x2 %0, %1, %2;" : "=l"(d) : "l"(a), "l"(b)); return d;
}

// ---------------- scratch (device globals; no allocation allowed) ----------------
static __device__ float g_buf2a[BB*C2*HWSZ];   // 205.5 MB
static __device__ float g_buf2b[BB*C2*HWSZ];   // 205.5 MB
static __device__ float g_bufc [BB*CCH*HWSZ];  // 102.8 MB
static __device__ float g_y    [BB*CCH*HWSZ];  // 102.8 MB
static __device__ float g_M    [C2*64*64];     // per-channel matrix, layout [c][in][out]
static __device__ float g_dctR [CCH*56];
static __device__ float g_dctC [CCH*56];
static __device__ float g_instS[BB*CCH], g_instQ[BB*CCH];
static __device__ float g_instMean[BB*CCH], g_instInv[BB*CCH];
static __device__ float g_scay[BB*CCH], g_z[BB*CCH];

// ---------------- tiny init kernels ----------------
__global__ void k_zero() {
    int t = threadIdx.x;
    if (t < BB*CCH) { g_instS[t] = 0.f; g_instQ[t] = 0.f; g_scay[t] = 0.f; }
}

__global__ void k_tables() {
    int t = blockIdx.x * blockDim.x + threadIdx.x;
    if (t >= CCH*56) return;
    int c = t / 56, i = t - c*56;
    const int mx[16] = {0,0,6,0,0,1,1,4,5,1,3,0,0,0,3,2};
    const int my[16] = {0,1,0,5,2,0,2,0,0,6,0,4,6,3,2,5};
    int g = c >> 2;
    int ux = mx[g]*8, uy = my[g]*8;
    float inv = rsqrtf(56.f);
    float rv = cosf((float)M_PI * ux * (i + 0.5f) / 56.f) * inv;
    if (ux) rv *= 1.41421356237f;
    float cv = cosf((float)M_PI * uy * (i + 0.5f) / 56.f) * inv;
    if (uy) cv *= 1.41421356237f;
    g_dctR[t] = rv; g_dctC[t] = cv;
}

// M layout: g_M[c*4096 + in*64 + out]  (k-major for the apply kernel)
__global__ void k_fftmat(const float* __restrict__ fw) {
    int t = blockIdx.x * blockDim.x + threadIdx.x;
    if (t >= C2*64) return;
    int c = t >> 6, in = t & 63, i0 = in >> 3, j0 = in & 7;
    const float c8[8] = {1.f, 0.70710678118f, 0.f, -0.70710678118f,
                         -1.f, -0.70710678118f, 0.f, 0.70710678118f};
    const float s8[8] = {0.f, 0.70710678118f, 1.f, 0.70710678118f,
                         0.f, -0.70710678118f, -1.f, -0.70710678118f};
    for (int p = 0; p < 8; p++) {
        float Gr[5], Gi[5];
        for (int v = 0; v < 5; v++) {
            float gr = 0.f, gi = 0.f;
            for (int u = 0; u < 8; u++) {
                int idx = ((u*(p - i0) - v*j0) % 8 + 8) % 8;
                float w = fw[c*40 + u*5 + v];
                gr += w * c8[idx]; gi += w * s8[idx];
            }
            Gr[v] = gr; Gi[v] = gi;
        }
        for (int q = 0; q < 8; q++) {
            float val = Gr[0] + ((q & 1) ? -Gr[4] : Gr[4]);
            for (int v = 1; v < 4; v++) {
                int k = (v*q) & 7;
                val += 2.f * (Gr[v]*c8[k] - Gi[v]*s8[k]);
            }
            g_M[c*4096 + in*64 + (p*8 + q)] = val * (1.f/64.f);
        }
    }
}

// =====================================================================
// Y-config GEMM: per-pixel channel-LN then 64 -> 128 conv1x1.
// 128 threads, 64 pixels/block.  gate=0: write 128 ch (+opt bias).
// gate=1: out[o] = (A[o]+b[o]) * (B[o]+b[o+64]),  o in [0,64).
// =====================================================================
__global__ __launch_bounds__(128) void k_lnY(
    const float* __restrict__ in, const float* __restrict__ w,
    const float* __restrict__ bias, const float* __restrict__ lnw,
    const float* __restrict__ lnb, float eps, float* __restrict__ out, int gate)
{
    __shared__ __align__(16) float  inT[64*64];   // [k][pix] 16KB
    __shared__ __align__(16) float4 wq[64*32];    // [k][o/4] 32KB
    int tid = threadIdx.x;
    for (int i = tid; i < 2048; i += 128) {
        int k = i >> 5, o4 = i & 31;
        const float* ws = w + o4*256 + k;
        wq[i] = make_float4(ws[0], ws[64], ws[128], ws[192]);
    }
    int pix0 = blockIdx.x*64;
    int b = pix0 / HWSZ, hw0 = pix0 - b*HWSZ;
    {
        int p = tid >> 1, h = tid & 1;
        const float* src = in + (b*64 + h*32)*HWSZ + hw0 + p;
        float v[32];
#pragma unroll
        for (int c = 0; c < 32; c++) v[c] = src[c*HWSZ];
        float s = 0.f;
#pragma unroll
        for (int c = 0; c < 32; c++) s += v[c];
        s += __shfl_xor_sync(0xffffffffu, s, 1);
        float mu = s * (1.f/64.f);
        float q = 0.f;
#pragma unroll
        for (int c = 0; c < 32; c++) { float d = v[c]-mu; q += d*d; }
        q += __shfl_xor_sync(0xffffffffu, q, 1);
        float is = rsqrtf(q*(1.f/64.f) + eps);
#pragma unroll
        for (int c = 0; c < 32; c++) {
            int ch = h*32 + c;
            inT[ch*64 + p] = (v[c]-mu)*is*__ldg(lnw+ch) + __ldg(lnb+ch);
        }
    }
    __syncthreads();

    int og = tid >> 3, pg = tid & 7;      // og 0..15, pg 0..7 (8 pixels)
    ull acc[2][4][4];
#pragma unroll
    for (int a = 0; a < 2; a++)
#pragma unroll
        for (int j = 0; j < 4; j++)
#pragma unroll
            for (int u = 0; u < 4; u++) acc[a][j][u] = 0ULL;

    const float* pI = inT + pg*8;
    for (int k = 0; k < 64; k++) {
        ulonglong2 va = *(const ulonglong2*)(pI + k*64);
        ulonglong2 vb = *(const ulonglong2*)(pI + k*64 + 4);
        float4 wa = wq[k*32 + og];
        float4 wb = wq[k*32 + 16 + og];
        float wav[4] = {wa.x, wa.y, wa.z, wa.w};
        float wbv[4] = {wb.x, wb.y, wb.z, wb.w};
#pragma unroll
        for (int j = 0; j < 4; j++) {
            ull wp = pack2(wav[j]);
            acc[0][j][0] = fma2(va.x, wp, acc[0][j][0]);
            acc[0][j][1] = fma2(va.y, wp, acc[0][j][1]);
            acc[0][j][2] = fma2(vb.x, wp, acc[0][j][2]);
            acc[0][j][3] = fma2(vb.y, wp, acc[0][j][3]);
            ull wp2 = pack2(wbv[j]);
            acc[1][j][0] = fma2(va.x, wp2, acc[1][j][0]);
            acc[1][j][1] = fma2(va.y, wp2, acc[1][j][1]);
            acc[1][j][2] = fma2(vb.x, wp2, acc[1][j][2]);
            acc[1][j][3] = fma2(vb.y, wp2, acc[1][j][3]);
        }
    }

    if (!gate) {
#pragma unroll
        for (int pass = 0; pass < 2; pass++)
#pragma unroll
            for (int j = 0; j < 4; j++) {
                int o = pass*64 + og*4 + j;
                ull b2 = bias ? pack2(__ldg(bias + o)) : 0ULL;
                float* dst = out + (b*128 + o)*HWSZ + hw0 + pg*8;
                ulonglong2 r0, r1;
                r0.x = add2(acc[pass][j][0], b2); r0.y = add2(acc[pass][j][1], b2);
                r1.x = add2(acc[pass][j][2], b2); r1.y = add2(acc[pass][j][3], b2);
                *(ulonglong2*)dst = r0;
                *(ulonglong2*)(dst + 4) = r1;
            }
    } else {
#pragma unroll
        for (int j = 0; j < 4; j++) {
            int o = og*4 + j;
            ull bA = pack2(__ldg(bias + o));
            ull bB = pack2(__ldg(bias + 64 + o));
            float* dst = out + (b*64 + o)*HWSZ + hw0 + pg*8;
            ulonglong2 r0, r1;
            r0.x = mul2(add2(acc[0][j][0], bA), add2(acc[1][j][0], bB));
            r0.y = mul2(add2(acc[0][j][1], bA), add2(acc[1][j][1], bB));
            r1.x = mul2(add2(acc[0][j][2], bA), add2(acc[1][j][2], bB));
            r1.y = mul2(add2(acc[0][j][3], bA), add2(acc[1][j][3], bB));
            *(ulonglong2*)dst = r0;
            *(ulonglong2*)(dst + 4) = r1;
        }
    }
}

// =====================================================================
// X-config GEMM: 64 -> 64 conv1x1 (+opt bias, +opt add). 256 thr, 128 px.
// =====================================================================
__global__ __launch_bounds__(256) void k_mmX(
    const float* __restrict__ in, const float* __restrict__ w,
    const float* __restrict__ bias, const float* __restrict__ add,
    float* __restrict__ out)
{
    __shared__ __align__(16) float  inT[8192];    // [k][pix] 32KB
    __shared__ __align__(16) float4 wq[1024];     // [k][o/4] 16KB
    int tid = threadIdx.x;
    for (int i = tid; i < 1024; i += 256) {
        int k = i >> 4, o4 = i & 15;
        const float* ws = w + o4*256 + k;
        wq[i] = make_float4(ws[0], ws[64], ws[128], ws[192]);
    }
    int pix0 = blockIdx.x*128;
    int b = pix0 / HWSZ, hw0 = pix0 - b*HWSZ;
    const float* src = in + b*64*HWSZ + hw0;
    for (int i = tid; i < 8192; i += 256) {
        int c = i >> 7, p = i & 127;
        inT[i] = src[c*HWSZ + p];
    }
    __syncthreads();

    int og = tid >> 4, pg = tid & 15;
    ull acc[4][4];
#pragma unroll
    for (int j = 0; j < 4; j++)
#pragma unroll
        for (int u = 0; u < 4; u++) acc[j][u] = 0ULL;

    const float* pI = inT + pg*8;
    for (int k = 0; k < 64; k++) {
        ulonglong2 va = *(const ulonglong2*)(pI + k*128);
        ulonglong2 vb = *(const ulonglong2*)(pI + k*128 + 4);
        float4 wv = wq[k*16 + og];
        float wav[4] = {wv.x, wv.y, wv.z, wv.w};
#pragma unroll
        for (int j = 0; j < 4; j++) {
            ull wp = pack2(wav[j]);
            acc[j][0] = fma2(va.x, wp, acc[j][0]);
            acc[j][1] = fma2(va.y, wp, acc[j][1]);
            acc[j][2] = fma2(vb.x, wp, acc[j][2]);
            acc[j][3] = fma2(vb.y, wp, acc[j][3]);
        }
    }
#pragma unroll
    for (int j = 0; j < 4; j++) {
        int o = og*4 + j;
        ull b2 = bias ? pack2(__ldg(bias + o)) : 0ULL;
        ull r0 = add2(acc[j][0], b2), r1 = add2(acc[j][1], b2);
        ull r2 = add2(acc[j][2], b2), r3 = add2(acc[j][3], b2);
        int off = (b*64 + o)*HWSZ + hw0 + pg*8;
        if (add) {
            const ulonglong2* av = (const ulonglong2*)(add + off);
            ulonglong2 a0 = av[0], a1 = av[1];
            r0 = add2(r0, a0.x); r1 = add2(r1, a0.y);
            r2 = add2(r2, a1.x); r3 = add2(r3, a1.y);
        }
        ulonglong2 s0, s1; s0.x = r0; s0.y = r1; s1.x = r2; s1.y = r3;
        *(ulonglong2*)(out + off) = s0;
        *(ulonglong2*)(out + off + 4) = s1;
    }
}

// conv3 on z-scaled t3 + residual:  out = x + beta * (W @ (t3*z) + bias)
__global__ __launch_bounds__(256) void k_c3X(
    const float* __restrict__ x, const float* __restrict__ w,
    const float* __restrict__ bias, const float* __restrict__ beta)
{
    __shared__ __align__(16) float  inT[8192];
    __shared__ __align__(16) float4 wq[1024];
    int tid = threadIdx.x;
    for (int i = tid; i < 1024; i += 256) {
        int k = i >> 4, o4 = i & 15;
        const float* ws = w + o4*256 + k;
        wq[i] = make_float4(ws[0], ws[64], ws[128], ws[192]);
    }
    int pix0 = blockIdx.x*128;
    int b = pix0 / HWSZ, hw0 = pix0 - b*HWSZ;
    const float* src = g_bufc + b*64*HWSZ + hw0;
    for (int i = tid; i < 8192; i += 256) {
        int c = i >> 7, p = i & 127;
        inT[i] = src[c*HWSZ + p] * g_z[b*64 + c];
    }
    __syncthreads();

    int og = tid >> 4, pg = tid & 15;
    ull acc[4][4];
#pragma unroll
    for (int j = 0; j < 4; j++)
#pragma unroll
        for (int u = 0; u < 4; u++) acc[j][u] = 0ULL;

    const float* pI = inT + pg*8;
    for (int k = 0; k < 64; k++) {
        ulonglong2 va = *(const ulonglong2*)(pI + k*128);
        ulonglong2 vb = *(const ulonglong2*)(pI + k*128 + 4);
        float4 wv = wq[k*16 + og];
        float wav[4] = {wv.x, wv.y, wv.z, wv.w};
#pragma unroll
        for (int j = 0; j < 4; j++) {
            ull wp = pack2(wav[j]);
            acc[j][0] = fma2(va.x, wp, acc[j][0]);
            acc[j][1] = fma2(va.y, wp, acc[j][1]);
            acc[j][2] = fma2(vb.x, wp, acc[j][2]);
            acc[j][3] = fma2(vb.y, wp, acc[j][3]);
        }
    }
#pragma unroll
    for (int j = 0; j < 4; j++) {
        int o = og*4 + j;
        ull b2 = pack2(__ldg(bias + o));
        ull bt = pack2(__ldg(beta + o));
        int off = (b*64 + o)*HWSZ + hw0 + pg*8;
        const ulonglong2* xv = (const ulonglong2*)(x + off);
        ulonglong2 x0 = xv[0], x1 = xv[1];
        ulonglong2 s0, s1;
        s0.x = fma2(add2(acc[j][0], b2), bt, x0.x);
        s0.y = fma2(add2(acc[j][1], b2), bt, x0.y);
        s1.x = fma2(add2(acc[j][2], b2), bt, x1.x);
        s1.y = fma2(add2(acc[j][3], b2), bt, x1.y);
        *(ulonglong2*)(g_buf2a + off) = s0;
        *(ulonglong2*)(g_buf2a + off + 4) = s1;
    }
}

// ---------------- depthwise 3x3 (+bias) with InstanceNorm stats ----------------
__global__ __launch_bounds__(256) void k_dw_stats(
    const float* __restrict__ in, const float* __restrict__ w,
    const float* __restrict__ bias, float* __restrict__ out)
{
    int bc = blockIdx.z;
    int c = bc & 127, b = bc >> 7;
    __shared__ float tile[10][34];
    __shared__ float redS[256], redQ[256];
    int tx0 = blockIdx.x*32, ty0 = blockIdx.y*8;
    int tid = threadIdx.y*32 + threadIdx.x;
    const float* src = in + bc*HWSZ;
    for (int i = tid; i < 340; i += 256) {
        int r = i/34, cc = i - r*34;
        int gy = ty0 + r - 1, gx = tx0 + cc - 1;
        tile[r][cc] = (gy >= 0 && gy < HH && gx >= 0 && gx < WWID) ? src[gy*WWID+gx] : 0.f;
    }
    __syncthreads();
    float acc = bias[c];
#pragma unroll
    for (int di = 0; di < 3; di++)
#pragma unroll
        for (int dj = 0; dj < 3; dj++)
            acc += w[c*9 + di*3 + dj] * tile[threadIdx.y+di][threadIdx.x+dj];
    out[bc*HWSZ + (ty0+threadIdx.y)*WWID + tx0 + threadIdx.x] = acc;

    if (c < 64) {
        redS[tid] = acc; redQ[tid] = acc*acc;
        __syncthreads();
        for (int s = 128; s > 0; s >>= 1) {
            if (tid < s) { redS[tid] += redS[tid+s]; redQ[tid] += redQ[tid+s]; }
            __syncthreads();
        }
        if (tid == 0) {
            atomicAdd(&g_instS[b*64 + c], redS[0]);
            atomicAdd(&g_instQ[b*64 + c], redQ[0]);
        }
    }
}

__global__ void k_instfin() {
    int t = blockIdx.x*blockDim.x + threadIdx.x;
    if (t < BB*CCH) {
        float m = g_instS[t] * (1.f/HWSZ);
        float v = g_instQ[t] * (1.f/HWSZ) - m*m;
        g_instMean[t] = m;
        g_instInv[t]  = rsqrtf(v + 1e-5f);
    }
}

// ---------------- instnorm(a)*g -> t3 (float4), DCT-weighted SCA pool ----------------
__global__ __launch_bounds__(256) void k_gate_sca4(
    const float* __restrict__ inw, const float* __restrict__ inb)
{
    int bc = blockIdx.y;
    int c = bc & 63, b = bc >> 6;
    int i4 = blockIdx.x*256 + threadIdx.x;          // quad index, < 12544
    const float4* A = (const float4*)(g_buf2b + (b*128 + c)*HWSZ);
    const float4* G = (const float4*)(g_buf2b + (b*128 + 64 + c)*HWSZ);
    float m = g_instMean[bc], iv = g_instInv[bc];
    float sw = inw[c], sb = inb[c];
    float4 a = A[i4], g = G[i4];
    float4 t;
    t.x = ((a.x - m)*iv*sw + sb) * g.x;
    t.y = ((a.y - m)*iv*sw + sb) * g.y;
    t.z = ((a.z - m)*iv*sw + sb) * g.z;
    t.w = ((a.w - m)*iv*sw + sb) * g.w;
    ((float4*)(g_bufc + bc*HWSZ))[i4] = t;
    int gy = i4 / 56, gx4 = i4 - gy*56;             // gx = gx4*4, gx>>2 == gx4
    float ws = (t.x + t.y + t.z + t.w) * g_dctR[c*56 + (gy >> 2)] * g_dctC[c*56 + gx4];
    __shared__ float red[256];
    red[threadIdx.x] = ws; __syncthreads();
    for (int s = 128; s > 0; s >>= 1) {
        if (threadIdx.x < s) red[threadIdx.x] += red[threadIdx.x+s];
        __syncthreads();
    }
    if (threadIdx.x == 0) atomicAdd(&g_scay[bc], red[0]);
}

__global__ void k_se(const float* __restrict__ fc1, const float* __restrict__ fc2) {
    int b = blockIdx.x, c = threadIdx.x;
    __shared__ float ys[64];
    ys[c] = g_scay[b*64 + c] * (1.f/16.f);
    __syncthreads();
    float h[4];
#pragma unroll
    for (int j = 0; j < 4; j++) {
        float s = 0.f;
#pragma unroll
        for (int k = 0; k < 64; k++) s += fc1[j*64 + k] * ys[k];
        h[j] = fmaxf(s, 0.f);
    }
    float z = 0.f;
#pragma unroll
    for (int j = 0; j < 4; j++) z += fc2[c*4 + j] * h[j];
    g_z[b*64 + c] = 1.f / (1.f + expf(-z));
}

// ---------------- per-patch spectral transform (M resident per plane) ----------------
__global__ __launch_bounds__(128) void k_fftapply_rb() {
    int bc = blockIdx.x;                 // b*128 + c
    int c  = bc & 127;
    __shared__ __align__(16) float Ms[4096];        // [in][out] 16KB
    __shared__ __align__(16) float pat[64*60];      // [in][patch] / outS reuse
    int tid = threadIdx.x;
    const float* msrc = g_M + c*4096;
    for (int i = tid; i < 4096; i += 128) Ms[i] = msrc[i];
    const float* src = g_buf2b + bc*HWSZ;
    float* dstp = g_buf2a + bc*HWSZ;
    int og = tid & 15, pg = tid >> 4;    // og 0..15 (4 out), pg 0..7 (8 patches, pg<7 active)
    for (int bp = 0; bp < 14; bp++) {
        for (int i = tid; i < 3584; i += 128) {
            int r = i / 224, wcol = i - r*224;
            int p = r & 7, band = r >> 3, pc = wcol >> 3, q = wcol & 7;
            pat[(p*8+q)*60 + band*28 + pc] = src[(bp*16 + r)*224 + wcol];
        }
        __syncthreads();
        ull acc[4][4];
#pragma unroll
        for (int j = 0; j < 4; j++)
#pragma unroll
            for (int u = 0; u < 4; u++) acc[j][u] = 0ULL;
        if (pg < 7) {
            const float* pI = pat + pg*8;
            for (int k = 0; k < 64; k++) {
                ulonglong2 va = *(const ulonglong2*)(pI + k*60);
                ulonglong2 vb = *(const ulonglong2*)(pI + k*60 + 4);
                float4 wv = *(const float4*)(Ms + k*64 + og*4);
                float wav[4] = {wv.x, wv.y, wv.z, wv.w};
#pragma unroll
                for (int j = 0; j < 4; j++) {
                    ull wp = pack2(wav[j]);
                    acc[j][0] = fma2(va.x, wp, acc[j][0]);
                    acc[j][1] = fma2(va.y, wp, acc[j][1]);
                    acc[j][2] = fma2(vb.x, wp, acc[j][2]);
                    acc[j][3] = fma2(vb.y, wp, acc[j][3]);
                }
            }
        }
        __syncthreads();
        if (pg < 7) {
#pragma unroll
            for (int j = 0; j < 4; j++) {
                int o = og*4 + j;
                ulonglong2 s0, s1;
                s0.x = acc[j][0]; s0.y = acc[j][1];
                s1.x = acc[j][2]; s1.y = acc[j][3];
                *(ulonglong2*)(pat + o*60 + pg*8) = s0;
                *(ulonglong2*)(pat + o*60 + pg*8 + 4) = s1;
            }
        }
        __syncthreads();
        for (int i = tid; i < 3584; i += 128) {
            int r = i / 224, wcol = i - r*224;
            int p = r & 7, band = r >> 3, pc = wcol >> 3, q = wcol & 7;
            dstp[(bp*16 + r)*224 + wcol] = pat[(p*8+q)*60 + band*28 + pc];
        }
        __syncthreads();
    }
}

// ---------------- DFFN depthwise 3x3 pair + gelu gate ----------------
__global__ __launch_bounds__(256) void k_dw_gelu(const float* __restrict__ w) {
    int bc = blockIdx.z;
    int c = bc & 63, b = bc >> 6;
    __shared__ float t1[10][34], t2[10][34];
    int tx0 = blockIdx.x*32, ty0 = blockIdx.y*8;
    int tid = threadIdx.y*32 + threadIdx.x;
    const float* s1 = g_buf2a + (b*128 + c)*HWSZ;
    const float* s2 = g_buf2a + (b*128 + 64 + c)*HWSZ;
    for (int i = tid; i < 340; i += 256) {
        int r = i/34, cc = i - r*34;
        int gy = ty0 + r - 1, gx = tx0 + cc - 1;
        bool ok = (gy >= 0 && gy < HH && gx >= 0 && gx < WWID);
        t1[r][cc] = ok ? s1[gy*WWID+gx] : 0.f;
        t2[r][cc] = ok ? s2[gy*WWID+gx] : 0.f;
    }
    __syncthreads();
    float d1 = 0.f, d2 = 0.f;
#pragma unroll
    for (int di = 0; di < 3; di++)
#pragma unroll
        for (int dj = 0; dj < 3; dj++) {
            d1 += w[c*9 + di*3 + dj]      * t1[threadIdx.y+di][threadIdx.x+dj];
            d2 += w[(64+c)*9 + di*3 + dj] * t2[threadIdx.y+di][threadIdx.x+dj];
        }
    float gel = 0.5f * d1 * (1.f + erff(d1 * 0.70710678118f));
    g_bufc[bc*HWSZ + (ty0+threadIdx.y)*WWID + tx0 + threadIdx.x] = gel * d2;
}

// ---------------- launch ----------------
extern "C" void kernel_launch(void* const* d_in, const int* in_sizes, int n_in,
                              void* d_out, int out_size)
{
    (void)in_sizes; (void)n_in; (void)out_size;
    const float* x       = (const float*)d_in[0];
    const float* n1_w    = (const float*)d_in[1];
    const float* n1_b    = (const float*)d_in[2];
    const float* conv1_w = (const float*)d_in[3];
    const float* conv1_b = (const float*)d_in[4];
    const float* conv2_w = (const float*)d_in[5];
    const float* conv2_b = (const float*)d_in[6];
    const float* in_w    = (const float*)d_in[7];
    const float* in_b    = (const float*)d_in[8];
    const float* fc1_w   = (const float*)d_in[9];
    const float* fc2_w   = (const float*)d_in[10];
    const float* conv3_w = (const float*)d_in[11];
    const float* conv3_b = (const float*)d_in[12];
    const float* beta    = (const float*)d_in[13];
    const float* n2n_w   = (const float*)d_in[14];
    const float* n2n_b   = (const float*)d_in[15];
    const float* conv4_w = (const float*)d_in[16];
    const float* conv4_b = (const float*)d_in[17];
    const float* conv5_w = (const float*)d_in[18];
    const float* conv5_b = (const float*)d_in[19];
    const float* ln_w    = (const float*)d_in[20];
    const float* ln_b    = (const float*)d_in[21];
    const float* pin_w   = (const float*)d_in[22];
    const float* dw_w    = (const float*)d_in[23];
    const float* fft_w   = (const float*)d_in[24];
    const float* pout_w  = (const float*)d_in[25];

    float *t2a, *t2b, *tc, *ty;
    cudaGetSymbolAddress((void**)&t2a, g_buf2a);
    cudaGetSymbolAddress((void**)&t2b, g_buf2b);
    cudaGetSymbolAddress((void**)&tc,  g_bufc);
    cudaGetSymbolAddress((void**)&ty,  g_y);

    const int YBLK = NPIX / 64;    // 6272
    const int XBLK = NPIX / 128;   // 3136

    k_zero<<<1, 512>>>();
    k_tables<<<28, 128>>>();
    k_fftmat<<<64, 128>>>(fft_w);

    // LN(n1) + conv1 (64->128)
    k_lnY<<<YBLK, 128>>>(x, conv1_w, conv1_b, n1_w, n1_b, 1e-6f, t2a, 0);

    // depthwise 3x3 + conv2 bias, InstanceNorm stats on 'a' half
    {
        dim3 g(7, 28, BB*C2), blk(32, 8);
        k_dw_stats<<<g, blk>>>(t2a, conv2_w, conv2_b, t2b);
    }
    k_instfin<<<4, 128>>>();

    // instnorm(a)*g -> t3, DCT-weighted SCA pooling
    {
        dim3 g(HWSZ/(4*256), BB*CCH);     // 49 x 512
        k_gate_sca4<<<g, 256>>>(in_w, in_b);
    }
    k_se<<<BB, 64>>>(fc1_w, fc2_w);

    // (t3*z) conv3 + residual -> g_buf2a
    k_c3X<<<XBLK, 256>>>(x, conv3_w, conv3_b, beta);
    // LN(n2n) + conv4 + SimpleGate -> g_bufc
    k_lnY<<<YBLK, 128>>>(t2a, conv4_w, conv4_b, n2n_w, n2n_b, 1e-6f, tc, 1);
    // conv5 -> y
    k_mmX<<<XBLK, 256>>>(tc, conv5_w, conv5_b, nullptr, ty);

    // DFFN: LN + pin (64->128) -> g_buf2b
    k_lnY<<<YBLK, 128>>>(ty, pin_w, nullptr, ln_w, ln_b, 1e-5f, t2b, 0);
    // patch spectral transform -> g_buf2a
    k_fftapply_rb<<<BB*C2, 128>>>();
    // depthwise pair + gelu gate -> g_bufc
    {
        dim3 g(7, 28, BB*CCH), blk(32, 8);
        k_dw_gelu<<<g, blk>>>(dw_w);
    }
    // pout + y -> d_out
    k_mmX<<<XBLK, 256>>>(tc, pout_w, nullptr, ty, (float*)d_out);
}